// round 15
// baseline (speedup 1.0000x reference)
#include <cuda_runtime.h>
#include <cuda_bf16.h>
#include <cstdint>

// y_t = d*y_{t-1} + x_t   per channel, y_{-1} = 0  (so y_0 = x_0)
// x: [BSZ=8, SEQ=4096, CH=1024] fp32, d: [CH] fp32, out same shape as x.
//
// Champion structure (R5/R14: 45.0us kernel / 51.4us wall, DRAM ~60%):
// one block per (batch, 32-channel group) column = 256 blocks,
// 256 threads = NSUB(8) t-subtiles x 32 channels, 2 blocks/SM (80 regs);
// 32 chunks of 128 timesteps; per chunk: register-local serial scan,
// one bar.sync (subAgg parity-double-buffered), every warp redundantly
// combines the 8 subtile aggregates (multiplier d^16) with a replicated
// carry register.
//
// R15 delta: STORE-ONLY streaming (__stcs). R9 tested __ldcs+__stcs jointly
// and regressed; the read-side evict-first was the suspect half (it
// de-buffers the read stream in L2). y is written once and never re-read,
// so write evict-first frees L2 allocate/capacity for reads at zero cost to
// the read path. Loads stay default-cached.

#define BSZ    8
#define SEQ    4096
#define CH     1024
#define TSUB   16
#define NSUB   8
#define NTHR   (NSUB * 32)          // 256
#define CHUNK  (TSUB * NSUB)        // 128
#define NCHUNK (SEQ / CHUNK)        // 32
#define CGRPS  (CH / 32)            // 32 channel groups per batch

__global__ __launch_bounds__(NTHR, 2)
void cummulsum_kernel(const float* __restrict__ x,
                      const float* __restrict__ d,
                      float* __restrict__ y)
{
    __shared__ float subAgg[2][NSUB][32];   // double-buffered by chunk parity

    const int tid  = threadIdx.x;
    const int lane = tid & 31;
    const int s    = tid >> 5;          // subtile index 0..7
    const int b    = blockIdx.x >> 5;   // batch 0..7
    const int cg   = blockIdx.x & 31;   // channel group 0..31
    const int c    = cg * 32 + lane;    // channel

    const float dc = __ldg(d + c);

    // Power table pw[i] = dc^(i+1); indexed in unrolled loops (no serial
    // multiply chain on the store path).
    float pw[TSUB];
    pw[0] = dc;
    #pragma unroll
    for (int i = 1; i < TSUB; i++) pw[i] = pw[i - 1] * dc;
    const float dT = pw[TSUB - 1];      // dc^16

    const size_t colBase = ((size_t)b * SEQ) * CH + (size_t)c;
    const float* xp = x + colBase + (size_t)(s * TSUB) * CH;
    float*       yp = y + colBase + (size_t)(s * TSUB) * CH;

    float carry = 0.0f;   // replicated per-warp running state (identical in all warps)

    float xa[TSUB];
    float xb[TSUB];

    // Prologue: load chunk 0 (default caching on reads)
    #pragma unroll
    for (int i = 0; i < TSUB; i++) xa[i] = xp[(size_t)i * CH];

    #pragma unroll 2
    for (int k = 0; k < NCHUNK; k++) {
        const int p = k & 1;

        // Prefetch next chunk (independent of everything below).
        const float* xpn = xp + (size_t)CHUNK * CH;
        if (k + 1 < NCHUNK) {
            #pragma unroll
            for (int i = 0; i < TSUB; i++) xb[i] = xpn[(size_t)i * CH];
        }

        // Local serial scan in place (zero initial condition)
        #pragma unroll
        for (int i = 1; i < TSUB; i++) xa[i] = fmaf(dc, xa[i - 1], xa[i]);

        subAgg[p][s][lane] = xa[TSUB - 1];
        __syncthreads();

        // Every warp redundantly scans all 8 aggregates; it uses the prefix
        // for its own subtile and updates its private replicated carry.
        float P;                         // state entering subtile s
        {
            float agg[NSUB];
            #pragma unroll
            for (int j = 0; j < NSUB; j++) agg[j] = subAgg[p][j][lane];
            float r = carry;
            P = r;                       // valid if s == 0
            #pragma unroll
            for (int j = 0; j < NSUB; j++) {
                r = fmaf(dT, r, agg[j]); // state entering subtile j+1
                if (j + 1 == s) P = r;
            }
            carry = r;                   // state entering next chunk
        }

        // Correction + store (streaming stores: y is never re-read)
        #pragma unroll
        for (int i = 0; i < TSUB; i++) {
            __stcs(yp + (size_t)i * CH, fmaf(pw[i], P, xa[i]));
        }

        // Rotate buffers
        #pragma unroll
        for (int i = 0; i < TSUB; i++) xa[i] = xb[i];

        xp += (size_t)CHUNK * CH;
        yp += (size_t)CHUNK * CH;
    }
}

extern "C" void kernel_launch(void* const* d_in, const int* in_sizes, int n_in,
                              void* d_out, int out_size)
{
    const float* x = (const float*)d_in[0];
    const float* d = (const float*)d_in[1];
    float*       y = (float*)d_out;
    (void)in_sizes; (void)n_in; (void)out_size;

    cummulsum_kernel<<<BSZ * CGRPS, NTHR>>>(x, d, y);
}

// round 16
// speedup vs baseline: 1.0241x; 1.0241x over previous
#include <cuda_runtime.h>
#include <cuda_bf16.h>
#include <cstdint>

// y_t = d*y_{t-1} + x_t   per channel, y_{-1} = 0  (so y_0 = x_0)
// x: [BSZ=8, SEQ=4096, CH=1024] fp32, d: [CH] fp32, out same shape as x.
//
// FINAL CHAMPION (R5 == R14, reproduced twice: 45.0us kernel / 51.4us wall,
// DRAM ~60%).
// One block per (batch, 32-channel group) column = 256 blocks,
// 256 threads = NSUB(8) t-subtiles x 32 channels, 2 blocks/SM (80 regs).
// 32 chunks of 128 timesteps; per chunk: register-local serial scan,
// one bar.sync (subAgg parity-double-buffered), then EVERY warp redundantly
// combines the 8 subtile aggregates (multiplier d^16) keeping a replicated
// carry register -> no warp-0 critical section, no second barrier.
//
// Roofline note: fully-interleaved 50/50 read/write stream, 268 MB total.
// Mixed-stream HBM efficiency (~75% of peak) puts the floor at ~45us kernel
// time, which this hits within 1%. Exhaustive knob sweep (R4,R6,R8-R12,R15):
// prefetch depth 2, cache hints (read and/or write), 32B/256B extents,
// 8 or 64 warps-equivalent shapes, and t-chained handoff all measured
// neutral-to-worse.

#define BSZ    8
#define SEQ    4096
#define CH     1024
#define TSUB   16
#define NSUB   8
#define NTHR   (NSUB * 32)          // 256
#define CHUNK  (TSUB * NSUB)        // 128
#define NCHUNK (SEQ / CHUNK)        // 32
#define CGRPS  (CH / 32)            // 32 channel groups per batch

__global__ __launch_bounds__(NTHR, 2)
void cummulsum_kernel(const float* __restrict__ x,
                      const float* __restrict__ d,
                      float* __restrict__ y)
{
    __shared__ float subAgg[2][NSUB][32];   // double-buffered by chunk parity

    const int tid  = threadIdx.x;
    const int lane = tid & 31;
    const int s    = tid >> 5;          // subtile index 0..7
    const int b    = blockIdx.x >> 5;   // batch 0..7
    const int cg   = blockIdx.x & 31;   // channel group 0..31
    const int c    = cg * 32 + lane;    // channel

    const float dc = __ldg(d + c);

    // Power table pw[i] = dc^(i+1); indexed in unrolled loops (no serial
    // multiply chain on the store path).
    float pw[TSUB];
    pw[0] = dc;
    #pragma unroll
    for (int i = 1; i < TSUB; i++) pw[i] = pw[i - 1] * dc;
    const float dT = pw[TSUB - 1];      // dc^16

    const size_t colBase = ((size_t)b * SEQ) * CH + (size_t)c;
    const float* xp = x + colBase + (size_t)(s * TSUB) * CH;
    float*       yp = y + colBase + (size_t)(s * TSUB) * CH;

    float carry = 0.0f;   // replicated per-warp running state (identical in all warps)

    float xa[TSUB];
    float xb[TSUB];

    // Prologue: load chunk 0
    #pragma unroll
    for (int i = 0; i < TSUB; i++) xa[i] = xp[(size_t)i * CH];

    #pragma unroll 2
    for (int k = 0; k < NCHUNK; k++) {
        const int p = k & 1;

        // Prefetch next chunk (independent of everything below).
        const float* xpn = xp + (size_t)CHUNK * CH;
        if (k + 1 < NCHUNK) {
            #pragma unroll
            for (int i = 0; i < TSUB; i++) xb[i] = xpn[(size_t)i * CH];
        }

        // Local serial scan in place (zero initial condition)
        #pragma unroll
        for (int i = 1; i < TSUB; i++) xa[i] = fmaf(dc, xa[i - 1], xa[i]);

        subAgg[p][s][lane] = xa[TSUB - 1];
        __syncthreads();

        // Every warp redundantly scans all 8 aggregates; it uses the prefix
        // for its own subtile and updates its private replicated carry.
        float P;                         // state entering subtile s
        {
            float agg[NSUB];
            #pragma unroll
            for (int j = 0; j < NSUB; j++) agg[j] = subAgg[p][j][lane];
            float r = carry;
            P = r;                       // valid if s == 0
            #pragma unroll
            for (int j = 0; j < NSUB; j++) {
                r = fmaf(dT, r, agg[j]); // state entering subtile j+1
                if (j + 1 == s) P = r;
            }
            carry = r;                   // state entering next chunk
        }

        // Correction + store: y_i = ylocal_i + dc^(i+1) * P
        #pragma unroll
        for (int i = 0; i < TSUB; i++) {
            yp[(size_t)i * CH] = fmaf(pw[i], P, xa[i]);
        }

        // Rotate buffers
        #pragma unroll
        for (int i = 0; i < TSUB; i++) xa[i] = xb[i];

        xp += (size_t)CHUNK * CH;
        yp += (size_t)CHUNK * CH;
    }
}

extern "C" void kernel_launch(void* const* d_in, const int* in_sizes, int n_in,
                              void* d_out, int out_size)
{
    const float* x = (const float*)d_in[0];
    const float* d = (const float*)d_in[1];
    float*       y = (float*)d_out;
    (void)in_sizes; (void)n_in; (void)out_size;

    cummulsum_kernel<<<BSZ * CGRPS, NTHR>>>(x, d, y);
}